// round 3
// baseline (speedup 1.0000x reference)
#include <cuda_runtime.h>
#include <cuda_bf16.h>

// ScalarMapping: out[b,c] = dot(x[b,c,:], W[c,:]) + bias[c]
// Reference shapes: B=256, C=512, D=784 (28*28). Pure HBM-bound streaming
// reduction (~411 MB of x per launch; W/bias are L2-resident).
//
// Design: warp-per-row. Each warp reduces one (b,c) row of D floats.
// Lanes load float4 strided by 32 -> fully coalesced 512B/instr, MLP>=12
// per lane (x+W pairs batched), warp-shuffle reduce, lane 0 writes.
//
// Shapes are taken from in_sizes/out_size at launch time (no hardcoding):
//   in_sizes[1] = C*D (W), in_sizes[2] = C (bias), out_size = B*C.

#define WARPS_PER_BLOCK 8
#define THREADS_PER_BLOCK (WARPS_PER_BLOCK * 32)

__global__ __launch_bounds__(THREADS_PER_BLOCK)
void scalar_mapping_kernel(const float* __restrict__ x,
                           const float* __restrict__ W,
                           const float* __restrict__ bias,
                           float* __restrict__ out,
                           int n_rows, int C, int D) {
    const int warp_id = threadIdx.x >> 5;
    const int lane    = threadIdx.x & 31;
    const int row     = blockIdx.x * WARPS_PER_BLOCK + warp_id;  // (b*C + c)
    if (row >= n_rows) return;

    const int c = row % C;

    const float* xr = x + (size_t)row * D;
    const float* wr = W + (size_t)c * D;

    float acc = 0.0f;

    const int d_vec = D >> 2;                // float4 count per row
    const int full  = d_vec & ~31;           // multiple of 32 float4s

    const float4* x4 = reinterpret_cast<const float4*>(xr);
    const float4* w4 = reinterpret_cast<const float4*>(wr);

    // Main body: batches of 6 float4-pairs per lane when available (D=784
    // gives exactly 6 full strips + tail). Compiler front-batches the LDGs.
    int i = lane;
    for (; i + 5 * 32 < full; i += 6 * 32) {
        float4 xv0 = __ldg(&x4[i        ]), wv0 = __ldg(&w4[i        ]);
        float4 xv1 = __ldg(&x4[i +   32 ]), wv1 = __ldg(&w4[i +   32 ]);
        float4 xv2 = __ldg(&x4[i + 2*32 ]), wv2 = __ldg(&w4[i + 2*32 ]);
        float4 xv3 = __ldg(&x4[i + 3*32 ]), wv3 = __ldg(&w4[i + 3*32 ]);
        float4 xv4 = __ldg(&x4[i + 4*32 ]), wv4 = __ldg(&w4[i + 4*32 ]);
        float4 xv5 = __ldg(&x4[i + 5*32 ]), wv5 = __ldg(&w4[i + 5*32 ]);
        acc = fmaf(xv0.x, wv0.x, acc); acc = fmaf(xv0.y, wv0.y, acc);
        acc = fmaf(xv0.z, wv0.z, acc); acc = fmaf(xv0.w, wv0.w, acc);
        acc = fmaf(xv1.x, wv1.x, acc); acc = fmaf(xv1.y, wv1.y, acc);
        acc = fmaf(xv1.z, wv1.z, acc); acc = fmaf(xv1.w, wv1.w, acc);
        acc = fmaf(xv2.x, wv2.x, acc); acc = fmaf(xv2.y, wv2.y, acc);
        acc = fmaf(xv2.z, wv2.z, acc); acc = fmaf(xv2.w, wv2.w, acc);
        acc = fmaf(xv3.x, wv3.x, acc); acc = fmaf(xv3.y, wv3.y, acc);
        acc = fmaf(xv3.z, wv3.z, acc); acc = fmaf(xv3.w, wv3.w, acc);
        acc = fmaf(xv4.x, wv4.x, acc); acc = fmaf(xv4.y, wv4.y, acc);
        acc = fmaf(xv4.z, wv4.z, acc); acc = fmaf(xv4.w, wv4.w, acc);
        acc = fmaf(xv5.x, wv5.x, acc); acc = fmaf(xv5.y, wv5.y, acc);
        acc = fmaf(xv5.z, wv5.z, acc); acc = fmaf(xv5.w, wv5.w, acc);
    }
    // Remaining full-warp strips
    for (; i < full; i += 32) {
        float4 xv = __ldg(&x4[i]), wv = __ldg(&w4[i]);
        acc = fmaf(xv.x, wv.x, acc); acc = fmaf(xv.y, wv.y, acc);
        acc = fmaf(xv.z, wv.z, acc); acc = fmaf(xv.w, wv.w, acc);
    }
    // Partial strip of float4s (d_vec % 32)
    if (i < d_vec) {
        float4 xv = __ldg(&x4[i]), wv = __ldg(&w4[i]);
        acc = fmaf(xv.x, wv.x, acc); acc = fmaf(xv.y, wv.y, acc);
        acc = fmaf(xv.z, wv.z, acc); acc = fmaf(xv.w, wv.w, acc);
    }
    // Scalar tail (D % 4) — zero for D=784 but keeps kernel shape-generic
    for (int j = (d_vec << 2) + lane; j < D; j += 32)
        acc = fmaf(__ldg(&xr[j]), __ldg(&wr[j]), acc);

    // Warp reduction
    #pragma unroll
    for (int off = 16; off > 0; off >>= 1)
        acc += __shfl_xor_sync(0xFFFFFFFFu, acc, off);

    if (lane == 0)
        out[row] = acc + __ldg(&bias[c]);
}

extern "C" void kernel_launch(void* const* d_in, const int* in_sizes, int n_in,
                              void* d_out, int out_size) {
    const float* x    = (const float*)d_in[0];
    const float* W    = (const float*)d_in[1];
    const float* bias = (const float*)d_in[2];
    float* out        = (float*)d_out;

    const int C      = in_sizes[2];             // bias element count
    const int D      = in_sizes[1] / C;         // W is [C, D]
    const int n_rows = out_size;                // B*C (out is [B,C,1])

    const int blocks = (n_rows + WARPS_PER_BLOCK - 1) / WARPS_PER_BLOCK;
    scalar_mapping_kernel<<<blocks, THREADS_PER_BLOCK>>>(x, W, bias, out,
                                                         n_rows, C, D);
}